// round 12
// baseline (speedup 1.0000x reference)
#include <cuda_runtime.h>
#include <cstdint>
#include <cstddef>

#define K_DIM 4096
#define O_DIM 11008
#define M_DIM 8192
#define BM 128
#define BN 128
#define THREADS 128
#define NX (O_DIM / BN)      // 86
#define K8 (K_DIM / 8)       // 512 k8-steps
#define NST (K8 / 2)         // 256 stages (2 k8 per stage)
#define PH 16                // panel height: wave working set ~70MB -> L2-resident

#define SMEM_TOTAL 65536     // 8 k8-slots x 8KB ring

// fragment-permuted scratch:
// chunk(m16, k8) = 512B: lane l (g=l>>2,t=l&3) holds {A[g][t],A[g+8][t],A[g][t+4],A[g+8][t+4]}
__device__ __align__(16) float g_xp[(size_t)M_DIM * K_DIM];
// chunk(n16, k8) = 512B: lane l holds {W[g][t],W[g][t+4],W[g+8][t],W[g+8][t+4]}
__device__ __align__(16) float g_wp[(size_t)O_DIM * K_DIM];

#define MT_BYTES ((size_t)(K_DIM / 8) * 512)   // bytes per 16-row band = 262144

__device__ __forceinline__ float to_tf32(float f) {
    unsigned u;
    asm("cvt.rna.tf32.f32 %0, %1;" : "=r"(u) : "f"(f));
    return __uint_as_float(u);
}

__device__ __forceinline__ uint32_t smem_u32(const void* p) {
    uint32_t a;
    asm("{ .reg .u64 t; cvta.to.shared.u64 t, %1; cvt.u32.u64 %0, t; }" : "=r"(a) : "l"(p));
    return a;
}

__device__ __forceinline__ void cp16(uint32_t dst, const void* src) {
    asm volatile("cp.async.cg.shared.global [%0], [%1], 16;" :: "r"(dst), "l"(src));
}

__device__ __forceinline__ float4 lds128(uint32_t addr) {
    float4 v;
    asm volatile("ld.shared.v4.f32 {%0,%1,%2,%3}, [%4];"
                 : "=f"(v.x), "=f"(v.y), "=f"(v.z), "=f"(v.w) : "r"(addr));
    return v;
}

// ---------- pre-pass 1: permute x into fragment order (RNA tf32 rounding) ----------
__global__ void __launch_bounds__(256)
permute_x(const float* __restrict__ x)
{
    __shared__ float sX[64][68];
    const int tid = threadIdx.x;
    const int bk = blockIdx.x;
    const int bm = blockIdx.y;

    const int row0 = tid >> 4, c4 = tid & 15;
    #pragma unroll
    for (int i = 0; i < 4; i++) {
        const int r = row0 + i * 16;
        float4 v = *(const float4*)(x + (size_t)(bm * 64 + r) * K_DIM + bk * 64 + c4 * 4);
        float4 o = make_float4(to_tf32(v.x), to_tf32(v.y), to_tf32(v.z), to_tf32(v.w));
        *(float4*)(&sX[r][c4 * 4]) = o;
    }
    __syncthreads();

    #pragma unroll
    for (int s = 0; s < 4; s++) {
        const int gs = s * 256 + tid;
        const int chunk = gs >> 5, lane = gs & 31;
        const int k8l = chunk & 7, m16l = chunk >> 3;
        const int g = lane >> 2, t = lane & 3;
        float4 o;
        o.x = sX[m16l * 16 + g    ][k8l * 8 + t    ];
        o.y = sX[m16l * 16 + 8 + g][k8l * 8 + t    ];
        o.z = sX[m16l * 16 + g    ][k8l * 8 + t + 4];
        o.w = sX[m16l * 16 + 8 + g][k8l * 8 + t + 4];
        const size_t m16g = (size_t)bm * 4 + m16l;
        const size_t k8g  = (size_t)bk * 8 + k8l;
        ((float4*)g_xp)[(m16g * K8 + k8g) * 32 + lane] = o;
    }
}

// ---------- pre-pass 2: dequant + permute W into fragment order ----------
__global__ void __launch_bounds__(256)
permute_w(const int* __restrict__ widx, const float* __restrict__ cb)
{
    __shared__ float sW[64][68];
    __shared__ float scb[256];
    const int tid = threadIdx.x;
    scb[tid] = to_tf32(cb[tid]);
    __syncthreads();

    const int bk = blockIdx.x;
    const int bo = blockIdx.y;

    const int row0 = tid >> 4, c4 = tid & 15;
    #pragma unroll
    for (int i = 0; i < 4; i++) {
        const int r = row0 + i * 16;
        int4 v = *(const int4*)(widx + (size_t)(bo * 64 + r) * K_DIM + bk * 64 + c4 * 4);
        float4 o = make_float4(scb[v.x], scb[v.y], scb[v.z], scb[v.w]);
        *(float4*)(&sW[r][c4 * 4]) = o;
    }
    __syncthreads();

    #pragma unroll
    for (int s = 0; s < 4; s++) {
        const int gs = s * 256 + tid;
        const int chunk = gs >> 5, lane = gs & 31;
        const int k8l = chunk & 7, n16l = chunk >> 3;
        const int g = lane >> 2, t = lane & 3;
        float4 o;
        o.x = sW[n16l * 16 + g    ][k8l * 8 + t    ];
        o.y = sW[n16l * 16 + g    ][k8l * 8 + t + 4];
        o.z = sW[n16l * 16 + 8 + g][k8l * 8 + t    ];
        o.w = sW[n16l * 16 + 8 + g][k8l * 8 + t + 4];
        const size_t n16g = (size_t)bo * 4 + n16l;
        const size_t k8g  = (size_t)bk * 8 + k8l;
        ((float4*)g_wp)[(n16g * K8 + k8g) * 32 + lane] = o;
    }
}

// ---------- GEMM: cp.async smem ring (fragment order) + reg double buffer ----------
__global__ void __launch_bounds__(THREADS, 2)
phirho_gemm_v11(const float* __restrict__ bias, float* __restrict__ out)
{
    extern __shared__ __align__(16) char smem[];
    const uint32_t sbase = smem_u32(smem);
    const int tid = threadIdx.x;

    // panel rasterization
    const int bid = blockIdx.x;
    const int per_panel = PH * NX;
    const int panel = bid / per_panel;
    const int r0 = bid - panel * per_panel;
    const int by = panel * PH + (r0 % PH);
    const int bx = r0 / PH;
    const int bm = by * BM;
    const int bn = bx * BN;

    const int w = tid >> 5, lane = tid & 31;
    const int wm = (w >> 1) * 64;
    const int wn = (w & 1) * 64;
    const int g = lane >> 2, t = lane & 3;

    // ---- producer setup: thread owns chunk = tid>>3 (0..7 A bands, 8..15 B bands),
    //      64B segment (tid&7)*64, for both k8 of each stage ----
    const int chunk = tid >> 3;
    const int seg = (tid & 7) * 64;
    const char* src;
    if (chunk < 8)
        src = (const char*)g_xp + ((size_t)((bm >> 4) + chunk)) * MT_BYTES + seg;
    else
        src = (const char*)g_wp + ((size_t)((bn >> 4) + (chunk - 8))) * MT_BYTES + seg;
    const uint32_t dstb = sbase + chunk * 512 + seg;
    int slot4 = 0;   // stage slot (0..3), 16KB each

#define FILL()                                                              \
    do {                                                                    \
        const uint32_t d = dstb + slot4 * 16384;                            \
        _Pragma("unroll")                                                   \
        for (int k8w = 0; k8w < 2; k8w++)                                   \
            _Pragma("unroll")                                               \
            for (int q = 0; q < 4; q++)                                     \
                cp16(d + k8w * 8192 + q * 16, src + k8w * 512 + q * 16);    \
        asm volatile("cp.async.commit_group;" ::: "memory");                \
        src += 1024;                                                        \
        slot4 = (slot4 + 1) & 3;                                            \
    } while (0)

    // ---- consumer LDS base addresses (slot 0, k8w 0); step offset = (k8&7)*8192 ----
    uint32_t aAddr[4], bAddr[4];
    #pragma unroll
    for (int mt = 0; mt < 4; mt++)
        aAddr[mt] = sbase + ((w >> 1) * 4 + mt) * 512 + lane * 16;
    #pragma unroll
    for (int np = 0; np < 4; np++)
        bAddr[np] = sbase + (8 + (w & 1) * 4 + np) * 512 + lane * 16;

    float acc[4][8][4];
    #pragma unroll
    for (int i = 0; i < 4; i++)
        #pragma unroll
        for (int j = 0; j < 8; j++)
            #pragma unroll
            for (int c = 0; c < 4; c++)
                acc[i][j][c] = 0.0f;

    float4 ab[2][4], bb[2][4];

#define LDFRAG(BUF, K8I)                                                    \
    do {                                                                    \
        const uint32_t off = ((uint32_t)(K8I) & 7u) << 13;                  \
        _Pragma("unroll")                                                   \
        for (int mt = 0; mt < 4; mt++) ab[BUF][mt] = lds128(aAddr[mt] + off); \
        _Pragma("unroll")                                                   \
        for (int np = 0; np < 4; np++) bb[BUF][np] = lds128(bAddr[np] + off); \
    } while (0)

#define MMAS(BUF)                                                           \
    do {                                                                    \
        _Pragma("unroll")                                                   \
        for (int mt = 0; mt < 4; mt++) {                                    \
            const unsigned a0 = __float_as_uint(ab[BUF][mt].x);             \
            const unsigned a1 = __float_as_uint(ab[BUF][mt].y);             \
            const unsigned a2 = __float_as_uint(ab[BUF][mt].z);             \
            const unsigned a3 = __float_as_uint(ab[BUF][mt].w);             \
            _Pragma("unroll")                                               \
            for (int nt = 0; nt < 8; nt++) {                                \
                const int np = nt >> 1;                                     \
                const unsigned b0 = (nt & 1) ? __float_as_uint(bb[BUF][np].z) \
                                             : __float_as_uint(bb[BUF][np].x); \
                const unsigned b1 = (nt & 1) ? __float_as_uint(bb[BUF][np].w) \
                                             : __float_as_uint(bb[BUF][np].y); \
                asm volatile(                                               \
                    "mma.sync.aligned.m16n8k8.row.col.f32.tf32.tf32.f32 "   \
                    "{%0,%1,%2,%3}, {%4,%5,%6,%7}, {%8,%9}, {%0,%1,%2,%3};\n" \
                    : "+f"(acc[mt][nt][0]), "+f"(acc[mt][nt][1]),           \
                      "+f"(acc[mt][nt][2]), "+f"(acc[mt][nt][3])            \
                    : "r"(a0), "r"(a1), "r"(a2), "r"(a3), "r"(b0), "r"(b1)); \
            }                                                               \
        }                                                                   \
    } while (0)

    // prologue: commit stages 0,1,2; wait stages 0,1; preload frags k8=0
    FILL(); FILL(); FILL();
    asm volatile("cp.async.wait_group 1;" ::: "memory");
    __syncthreads();
    LDFRAG(0, 0);

    for (int st = 0; st < NST; st++) {
        // commit stage st+3 (slot held stage st-1; all warps passed last barrier)
        if (st + 3 < NST) FILL();

        const int k8a = 2 * st;
        // k8a: preload k8a+1 (same stage), MMA buf0
        LDFRAG(1, k8a + 1);
        MMAS(0);
        // k8a+1: preload k8a+2 (stage st+1, completed by previous wait), MMA buf1
        if (st + 1 < NST) LDFRAG(0, k8a + 2);
        MMAS(1);

        if (st + 1 < NST) {
            if (st < NST - 4)
                asm volatile("cp.async.wait_group 1;" ::: "memory");
            else
                asm volatile("cp.async.wait_group 0;" ::: "memory");
            __syncthreads();
        }
    }

    // epilogue: bias add + streaming fp32 store (avoid L2 pollution)
    #pragma unroll
    for (int nt = 0; nt < 8; nt++) {
        const int col = bn + wn + nt * 8 + t * 2;
        const float b0 = bias[col];
        const float b1 = bias[col + 1];
        #pragma unroll
        for (int mt = 0; mt < 4; mt++) {
            const int row = bm + wm + mt * 16 + g;
            float2 v0 = make_float2(acc[mt][nt][0] + b0, acc[mt][nt][1] + b1);
            float2 v1 = make_float2(acc[mt][nt][2] + b0, acc[mt][nt][3] + b1);
            __stcs((float2*)(out + (size_t)row       * O_DIM + col), v0);
            __stcs((float2*)(out + (size_t)(row + 8) * O_DIM + col), v1);
        }
    }
}

extern "C" void kernel_launch(void* const* d_in, const int* in_sizes, int n_in,
                              void* d_out, int out_size) {
    const float* x    = (const float*)d_in[0];
    const int*   widx = (const int*)  d_in[1];
    const float* cb   = (const float*)d_in[2];
    const float* bias = (const float*)d_in[3];
    float* out = (float*)d_out;

    const int ntok = in_sizes[0] / K_DIM;   // 8192
    const int ny = ntok / BM;               // 64

    static bool attr_set = false;
    if (!attr_set) {
        cudaFuncSetAttribute(phirho_gemm_v11,
                             cudaFuncAttributeMaxDynamicSharedMemorySize, SMEM_TOTAL);
        attr_set = true;
    }

    // pre-pass: permute x and dequant+permute W into fragment layouts
    permute_x<<<dim3(K_DIM / 64, ntok / 64), 256>>>(x);
    permute_w<<<dim3(K_DIM / 64, O_DIM / 64), 256>>>(widx, cb);

    // GEMM
    dim3 grid(NX * ny);                     // 5504
    phirho_gemm_v11<<<grid, THREADS, SMEM_TOTAL>>>(bias, out);
}

// round 13
// speedup vs baseline: 1.3755x; 1.3755x over previous
#include <cuda_runtime.h>
#include <cstdint>
#include <cstddef>

#define K_DIM 4096
#define O_DIM 11008
#define M_DIM 8192
#define BM 128
#define BN 128
#define THREADS 128
#define NX (O_DIM / BN)      // 86
#define K8 (K_DIM / 8)       // 512 k8-steps
#define PH 16                // panel height: wave working set ~70MB -> L2-resident

// fragment-permuted scratch:
// chunk(m16, k8) = 512B: lane l (g=l>>2,t=l&3) holds {A[g][t],A[g+8][t],A[g][t+4],A[g+8][t+4]}
__device__ __align__(16) float g_xp[(size_t)M_DIM * K_DIM];
// chunk(n16, k8) = 512B: lane l holds {W[g][t],W[g][t+4],W[g+8][t],W[g+8][t+4]}
__device__ __align__(16) float g_wp[(size_t)O_DIM * K_DIM];

#define MT_BYTES ((size_t)(K_DIM / 8) * 512)   // bytes per 16-row band = 262144

__device__ __forceinline__ float to_tf32(float f) {
    unsigned u;
    asm("cvt.rna.tf32.f32 %0, %1;" : "=r"(u) : "f"(f));
    return __uint_as_float(u);
}

__device__ __forceinline__ float4 ldg_nc4(const void* p) {
    float4 v;
    asm volatile("ld.global.nc.v4.f32 {%0,%1,%2,%3}, [%4];"
                 : "=f"(v.x), "=f"(v.y), "=f"(v.z), "=f"(v.w) : "l"(p));
    return v;
}

// ---------- pre-pass 1: permute x into fragment order (RNA tf32 rounding) ----------
__global__ void __launch_bounds__(256)
permute_x(const float* __restrict__ x)
{
    __shared__ float sX[64][68];
    const int tid = threadIdx.x;
    const int bk = blockIdx.x;       // 64-col K block
    const int bm = blockIdx.y;       // 64-row M block

    const int row0 = tid >> 4, c4 = tid & 15;
    #pragma unroll
    for (int i = 0; i < 4; i++) {
        const int r = row0 + i * 16;
        float4 v = *(const float4*)(x + (size_t)(bm * 64 + r) * K_DIM + bk * 64 + c4 * 4);
        float4 o = make_float4(to_tf32(v.x), to_tf32(v.y), to_tf32(v.z), to_tf32(v.w));
        *(float4*)(&sX[r][c4 * 4]) = o;
    }
    __syncthreads();

    #pragma unroll
    for (int s = 0; s < 4; s++) {
        const int gs = s * 256 + tid;
        const int chunk = gs >> 5, lane = gs & 31;
        const int k8l = chunk & 7, m16l = chunk >> 3;
        const int g = lane >> 2, t = lane & 3;
        float4 o;
        o.x = sX[m16l * 16 + g    ][k8l * 8 + t    ];
        o.y = sX[m16l * 16 + 8 + g][k8l * 8 + t    ];
        o.z = sX[m16l * 16 + g    ][k8l * 8 + t + 4];
        o.w = sX[m16l * 16 + 8 + g][k8l * 8 + t + 4];
        const size_t m16g = (size_t)bm * 4 + m16l;
        const size_t k8g  = (size_t)bk * 8 + k8l;
        ((float4*)g_xp)[(m16g * K8 + k8g) * 32 + lane] = o;
    }
}

// ---------- pre-pass 2: dequant + permute W into fragment order ----------
__global__ void __launch_bounds__(256)
permute_w(const int* __restrict__ widx, const float* __restrict__ cb)
{
    __shared__ float sW[64][68];
    __shared__ float scb[256];
    const int tid = threadIdx.x;
    scb[tid] = to_tf32(cb[tid]);
    __syncthreads();

    const int bk = blockIdx.x;       // 64-col K block
    const int bo = blockIdx.y;       // 64-row O block

    const int row0 = tid >> 4, c4 = tid & 15;
    #pragma unroll
    for (int i = 0; i < 4; i++) {
        const int r = row0 + i * 16;
        int4 v = *(const int4*)(widx + (size_t)(bo * 64 + r) * K_DIM + bk * 64 + c4 * 4);
        float4 o = make_float4(scb[v.x], scb[v.y], scb[v.z], scb[v.w]);
        *(float4*)(&sW[r][c4 * 4]) = o;
    }
    __syncthreads();

    #pragma unroll
    for (int s = 0; s < 4; s++) {
        const int gs = s * 256 + tid;
        const int chunk = gs >> 5, lane = gs & 31;
        const int k8l = chunk & 7, n16l = chunk >> 3;
        const int g = lane >> 2, t = lane & 3;
        float4 o;
        o.x = sW[n16l * 16 + g    ][k8l * 8 + t    ];
        o.y = sW[n16l * 16 + g    ][k8l * 8 + t + 4];
        o.z = sW[n16l * 16 + 8 + g][k8l * 8 + t    ];
        o.w = sW[n16l * 16 + 8 + g][k8l * 8 + t + 4];
        const size_t n16g = (size_t)bo * 4 + n16l;
        const size_t k8g  = (size_t)bk * 8 + k8l;
        ((float4*)g_wp)[(n16g * K8 + k8g) * 32 + lane] = o;
    }
}

// ---------- GEMM: no smem; TRIPLE-buffered register frags (distance-2 loads) ----------
__global__ void __launch_bounds__(THREADS, 2)
phirho_gemm_v13(const float* __restrict__ bias, float* __restrict__ out)
{
    const int tid = threadIdx.x;

    // panel rasterization
    const int bid = blockIdx.x;
    const int per_panel = PH * NX;
    const int panel = bid / per_panel;
    const int r0 = bid - panel * per_panel;
    const int by = panel * PH + (r0 % PH);
    const int bx = r0 / PH;
    const int bm = by * BM;
    const int bn = bx * BN;

    const int w = tid >> 5, lane = tid & 31;
    const int wm = (w >> 1) * 64;
    const int wn = (w & 1) * 64;
    const int g = lane >> 2, t = lane & 3;

    // per-warp fragment pointers (advance 512B per k8 step)
    const char* aPtr = (const char*)g_xp +
        ((size_t)((bm + wm) >> 4) * K8 * 512) + (size_t)lane * 16;
    const char* bPtr = (const char*)g_wp +
        ((size_t)((bn + wn) >> 4) * K8 * 512) + (size_t)lane * 16;

    float acc[4][8][4];
    #pragma unroll
    for (int i = 0; i < 4; i++)
        #pragma unroll
        for (int j = 0; j < 8; j++)
            #pragma unroll
            for (int c = 0; c < 4; c++)
                acc[i][j][c] = 0.0f;

    // three fragment buffers; step j uses buffer (j mod 3); loads run 2 steps ahead
    float4 a0[4], b0[4], a1[4], b1[4], a2[4], b2[4];

#define LD_INTO(AB, BB, OFF)                                               \
    do {                                                                   \
        _Pragma("unroll")                                                  \
        for (int mt = 0; mt < 4; mt++) {                                   \
            AB[mt] = ldg_nc4(aPtr + (size_t)mt * MT_BYTES + (OFF));        \
            BB[mt] = ldg_nc4(bPtr + (size_t)mt * MT_BYTES + (OFF));        \
        }                                                                  \
    } while (0)

#define MMAS(AB, BB)                                                       \
    do {                                                                   \
        _Pragma("unroll")                                                  \
        for (int mt = 0; mt < 4; mt++) {                                   \
            const unsigned ra0 = __float_as_uint(AB[mt].x);                \
            const unsigned ra1 = __float_as_uint(AB[mt].y);                \
            const unsigned ra2 = __float_as_uint(AB[mt].z);                \
            const unsigned ra3 = __float_as_uint(AB[mt].w);                \
            _Pragma("unroll")                                              \
            for (int nt = 0; nt < 8; nt++) {                               \
                const int np = nt >> 1;                                    \
                const unsigned rb0 = (nt & 1) ? __float_as_uint(BB[np].z)  \
                                              : __float_as_uint(BB[np].x); \
                const unsigned rb1 = (nt & 1) ? __float_as_uint(BB[np].w)  \
                                              : __float_as_uint(BB[np].y); \
                asm volatile(                                              \
                    "mma.sync.aligned.m16n8k8.row.col.f32.tf32.tf32.f32 "  \
                    "{%0,%1,%2,%3}, {%4,%5,%6,%7}, {%8,%9}, {%0,%1,%2,%3};\n" \
                    : "+f"(acc[mt][nt][0]), "+f"(acc[mt][nt][1]),          \
                      "+f"(acc[mt][nt][2]), "+f"(acc[mt][nt][3])           \
                    : "r"(ra0), "r"(ra1), "r"(ra2), "r"(ra3),              \
                      "r"(rb0), "r"(rb1));                                 \
            }                                                              \
        }                                                                  \
    } while (0)

    // prologue: steps 0,1 into buffers 0,1
    LD_INTO(a0, b0, 0);
    LD_INTO(a1, b1, 512);

    // main loop: 170 iterations x 3 steps = 510; step j consumes buf (j%3),
    // and loads j+2 into buf ((j+2)%3). Pointers advance 1536B per iteration.
    for (int it = 0; it < 170; it++) {
        LD_INTO(a2, b2, 1024);   // step j+2 -> buf2
        MMAS(a0, b0);            // step j   (buf0)
        LD_INTO(a0, b0, 1536);   // step j+3 -> buf0
        MMAS(a1, b1);            // step j+1 (buf1)
        LD_INTO(a1, b1, 2048);   // step j+4 -> buf1
        MMAS(a2, b2);            // step j+2 (buf2)
        aPtr += 1536;
        bPtr += 1536;
        if ((it & 15) == 15) __syncthreads();   // re-converge warps for L1 reuse
    }
    // tail: steps 510 (buf0), 511 (buf1) — already loaded in final iteration
    MMAS(a0, b0);
    MMAS(a1, b1);

    // epilogue: bias add + fp32 store (all tiles full)
    #pragma unroll
    for (int nt = 0; nt < 8; nt++) {
        const int col = bn + wn + nt * 8 + t * 2;
        const float vb0 = bias[col];
        const float vb1 = bias[col + 1];
        #pragma unroll
        for (int mt = 0; mt < 4; mt++) {
            const int row = bm + wm + mt * 16 + g;
            float2 v0 = make_float2(acc[mt][nt][0] + vb0, acc[mt][nt][1] + vb1);
            float2 v1 = make_float2(acc[mt][nt][2] + vb0, acc[mt][nt][3] + vb1);
            *(float2*)(out + (size_t)row       * O_DIM + col) = v0;
            *(float2*)(out + (size_t)(row + 8) * O_DIM + col) = v1;
        }
    }
}

extern "C" void kernel_launch(void* const* d_in, const int* in_sizes, int n_in,
                              void* d_out, int out_size) {
    const float* x    = (const float*)d_in[0];
    const int*   widx = (const int*)  d_in[1];
    const float* cb   = (const float*)d_in[2];
    const float* bias = (const float*)d_in[3];
    float* out = (float*)d_out;

    const int ntok = in_sizes[0] / K_DIM;   // 8192
    const int ny = ntok / BM;               // 64

    // pre-pass: permute x and dequant+permute W into fragment layouts
    permute_x<<<dim3(K_DIM / 64, ntok / 64), 256>>>(x);
    permute_w<<<dim3(K_DIM / 64, O_DIM / 64), 256>>>(widx, cb);

    // GEMM
    dim3 grid(NX * ny);                     // 5504
    phirho_gemm_v13<<<grid, THREADS>>>(bias, out);
}